// round 11
// baseline (speedup 1.0000x reference)
#include <cuda_runtime.h>
#include <cstdint>

#define BB   32
#define SS   1024
#define HH   256
#define G4   1024   // 4*H
#define H2   512    // 2*H

typedef unsigned long long ull;

// ---------------- f32x2 helpers (Blackwell packed fp32, 2 MAC/inst) -------
__device__ __forceinline__ ull ffma2(ull a, ull b, ull c)
{
    ull d;
    asm("fma.rn.f32x2 %0, %1, %2, %3;" : "=l"(d) : "l"(a), "l"(b), "l"(c));
    return d;
}
__device__ __forceinline__ ull add2(ull a, ull b)
{
    ull d;
    asm("add.rn.f32x2 %0, %1, %2;" : "=l"(d) : "l"(a), "l"(b));
    return d;
}
__device__ __forceinline__ ull pack_dup(float a)
{
    ull d;
    unsigned u = __float_as_uint(a);
    asm("mov.b64 %0, {%1, %1};" : "=l"(d) : "r"(u));
    return d;
}
__device__ __forceinline__ float2 unpack2(ull v)
{
    unsigned lo, hi;
    asm("mov.b64 {%0, %1}, %2;" : "=r"(lo), "=r"(hi) : "l"(v));
    return make_float2(__uint_as_float(lo), __uint_as_float(hi));
}

// ---------------- scoped release/acquire flag ops -------------------------
__device__ __forceinline__ void st_release_gpu(int* p, int v)
{
    asm volatile("st.release.gpu.global.u32 [%0], %1;" :: "l"(p), "r"(v) : "memory");
}
__device__ __forceinline__ int ld_acquire_gpu(const int* p)
{
    int v;
    asm volatile("ld.acquire.gpu.global.u32 %0, [%1];" : "=r"(v) : "l"(p) : "memory");
    return v;
}

// ------------------------- scratch (device globals; no allocs) -------------
// gates in recurrence layout: [s][cb(64)][b(32)][16]  (16 = gate*4+u)
__device__ float g_gates_f[(size_t)SS * BB * G4];   // 128 MB
__device__ float g_gates_b[(size_t)SS * BB * G4];   // 128 MB
__device__ float g_xout  [(size_t)SS * BB * H2];    //  64 MB (layer-0 output)
// replicated flags: [layer][dir][consumer(64)][producer(64)]
__device__ int   g_flags [2 * 2 * 64 * 64];
// h exchange, swizzled float4 layout: [dir][parity][j(8)][i(8)][kc(8)][bg(4)]
__device__ float g_hx    [2 * 2 * 2048 * 4];

// --------------------------------------------------------------------------
__global__ void zero_flags_k()
{
    int i = blockIdx.x * blockDim.x + threadIdx.x;
    if (i < 2 * 2 * 64 * 64) g_flags[i] = 0;
}

// --------------------------------------------------------------------------
// x-GEMM (unchanged from R8 — measured 65.8% fma): tiles 128x128, f32x2,
// pipelined LDG; blockIdx.z selects fwd/bwd weight set + output buffer.
__global__ void __launch_bounds__(256) gates_gemm(
    const float* __restrict__ A,
    const float* __restrict__ Wf, const float* __restrict__ bihf, const float* __restrict__ bhhf,
    const float* __restrict__ Wb, const float* __restrict__ bihb, const float* __restrict__ bhhb,
    float* __restrict__ Cf, float* __restrict__ Cb,
    int K, int a_mode)
{
    __shared__ __align__(16) float As[16][132];
    __shared__ __align__(16) float Bs[16][132];

    const int z = blockIdx.z;
    const float* W   = z ? Wb   : Wf;
    const float* bih = z ? bihb : bihf;
    const float* bhh = z ? bhhb : bhhf;
    float* C2        = z ? Cb   : Cf;

    const int tid = threadIdx.x;
    const int tx = tid & 15;
    const int ty = tid >> 4;
    const int m0 = blockIdx.y * 128;
    const int n0 = blockIdx.x * 128;

    const int lr = tid >> 2;        // 0..63
    const int lc = (tid & 3) << 2;  // 0,4,8,12

    const float* arow0;
    const float* arow1;
    {
        int m  = m0 + lr;
        int m2 = m + 64;
        if (a_mode == 0) {
            int s = m >> 5, b = m & 31;
            arow0 = A + ((size_t)b * SS + s) * K;
            s = m2 >> 5; b = m2 & 31;
            arow1 = A + ((size_t)b * SS + s) * K;
        } else {
            arow0 = A + (size_t)m  * K;
            arow1 = A + (size_t)m2 * K;
        }
    }
    const float* wrow0 = W + (size_t)(n0 + lr)      * K;
    const float* wrow1 = W + (size_t)(n0 + lr + 64) * K;

    ull accp[8][4];
#pragma unroll
    for (int i = 0; i < 8; ++i)
#pragma unroll
        for (int j = 0; j < 4; ++j) accp[i][j] = 0ull;

    const int KT = K >> 4;

    float4 a0 = *(const float4*)(arow0 + lc);
    float4 a1 = *(const float4*)(arow1 + lc);
    float4 b0 = *(const float4*)(wrow0 + lc);
    float4 b1 = *(const float4*)(wrow1 + lc);

    for (int kt = 0; kt < KT; ++kt) {
        __syncthreads();
        As[lc + 0][lr] = a0.x; As[lc + 1][lr] = a0.y; As[lc + 2][lr] = a0.z; As[lc + 3][lr] = a0.w;
        As[lc + 0][lr + 64] = a1.x; As[lc + 1][lr + 64] = a1.y; As[lc + 2][lr + 64] = a1.z; As[lc + 3][lr + 64] = a1.w;
        Bs[lc + 0][lr] = b0.x; Bs[lc + 1][lr] = b0.y; Bs[lc + 2][lr] = b0.z; Bs[lc + 3][lr] = b0.w;
        Bs[lc + 0][lr + 64] = b1.x; Bs[lc + 1][lr + 64] = b1.y; Bs[lc + 2][lr + 64] = b1.z; Bs[lc + 3][lr + 64] = b1.w;
        __syncthreads();
        if (kt + 1 < KT) {
            int k0 = (kt + 1) << 4;
            a0 = *(const float4*)(arow0 + k0 + lc);
            a1 = *(const float4*)(arow1 + k0 + lc);
            b0 = *(const float4*)(wrow0 + k0 + lc);
            b1 = *(const float4*)(wrow1 + k0 + lc);
        }
#pragma unroll
        for (int k = 0; k < 16; ++k) {
            float4 af0 = *(const float4*)&As[k][ty * 4];
            float4 af1 = *(const float4*)&As[k][64 + ty * 4];
            ulonglong2 bv0 = *(const ulonglong2*)&Bs[k][tx * 4];
            ulonglong2 bv1 = *(const ulonglong2*)&Bs[k][64 + tx * 4];
            ull bp[4] = {bv0.x, bv0.y, bv1.x, bv1.y};
            float a_[8] = {af0.x, af0.y, af0.z, af0.w, af1.x, af1.y, af1.z, af1.w};
#pragma unroll
            for (int i = 0; i < 8; ++i) {
                ull ad = pack_dup(a_[i]);
#pragma unroll
                for (int j = 0; j < 4; ++j)
                    accp[i][j] = ffma2(ad, bp[j], accp[i][j]);
            }
        }
    }

#pragma unroll
    for (int qi = 0; qi < 2; ++qi) {
#pragma unroll
        for (int i = 0; i < 4; ++i) {
            int m = m0 + qi * 64 + ty * 4 + i;
            int s = m >> 5, b = m & 31;
#pragma unroll
            for (int qj = 0; qj < 2; ++qj) {
                int n = n0 + qj * 64 + tx * 4;
                float2 p0 = unpack2(accp[qi * 4 + i][qj * 2 + 0]);
                float2 p1 = unpack2(accp[qi * 4 + i][qj * 2 + 1]);
                float4 v;
                v.x = p0.x + bih[n + 0] + bhh[n + 0];
                v.y = p0.y + bih[n + 1] + bhh[n + 1];
                v.z = p1.x + bih[n + 2] + bhh[n + 2];
                v.w = p1.y + bih[n + 3] + bhh[n + 3];
                int g  = n >> 8;
                int ub = (n & 255) >> 2;
                *(float4*)&C2[(((size_t)s * 64 + ub) * 32 + b) * 16 + g * 4] = v;
            }
        }
    }
}

// --------------------------------------------------------------------------
// Recurrence v3: 128 CTAs (blockIdx<64: fwd), 128 threads (4 warps).
// Warp rg = gate rg; lane = (bg in 4, kc in 8). Each lane: 8 batches x 4 rows
// over a 32-k slice; shfl_xor butterfly reduces over kc (3 rounds).
// W: bank-swizzled smem (conflict-free). h: direct __ldcg from swizzled
// global exchange buffer [j][i][kc][bg] float4 (nL=4 coalescing, no smem).
__device__ __forceinline__ float sigm_f(float x)
{
    float e = __expf(-x);
    return __fdividef(1.f, 1.f + e);
}
__device__ __forceinline__ float tanh_f(float x)
{
    float xc = fminf(fmaxf(x, -30.f), 30.f);
    float e = __expf(-2.f * xc);
    return __fdividef(1.f - e, 1.f + e);
}

__global__ void __launch_bounds__(128) lstm_recur(
    const float* __restrict__ gatesF2, const float* __restrict__ gatesB2,
    const float* __restrict__ WhhF, const float* __restrict__ WhhB,
    const float* __restrict__ mask,
    float* __restrict__ xout,
    float* __restrict__ hn_out, float* __restrict__ cn_out,
    int* __restrict__ flags,        // [dir][cons64][prod64]
    float* __restrict__ hx,         // [dir][parity][2048] float4
    int out_bs)
{
    __shared__ __align__(16) float sh_wp[4096];  // [k 256][rg 4][u 4], XOR-swizzled
    __shared__ __align__(16) float sh_g[32 * 18];

    const int tid = threadIdx.x;
    const int dir = blockIdx.x >> 6;
    const int cb  = blockIdx.x & 63;
    const int u0  = cb * 4;
    const int rg  = tid >> 5;       // warp = gate
    const int lane = tid & 31;
    const int bg  = lane >> 3;      // batch group (4)
    const int kc  = lane & 7;       // k chunk (8)

    const float* gates2 = dir ? gatesB2 : gatesF2;
    const float* Whh    = dir ? WhhB    : WhhF;
    int* fl_my   = flags + (dir * 64 + cb) * 64;
    int* fl_base = flags + dir * 64 * 64;

    // W into swizzled smem: word = k*16 + g*4 + u, XOR'd by ((k>>5)<<2)
    for (int idx = tid; idx < 4096; idx += 128) {
        int k = idx >> 4;
        int rl = idx & 15;            // g*4 + u
        int g = rl >> 2, uu = rl & 3;
        float v = Whh[(size_t)(g * HH + u0 + uu) * HH + k];
        sh_wp[idx ^ ((k >> 5) << 2)] = v;
    }
    __syncthreads();

    const int hoff = kc * 4 + bg;                 // lane offset in h buffer
    float4 c4 = make_float4(0.f, 0.f, 0.f, 0.f);  // cell state (tid<32)

    // producer store index for cell thread b = tid (<32):
    const int pidx = (cb & 7) * 256 + (tid & 7) * 32 + (cb >> 3) * 4 + (tid >> 3);

    for (int t = 0; t < SS; ++t) {
        const int s = dir ? (SS - 1 - t) : t;

        // cell-thread early loads (independent of the wait)
        float4 gxa, gxb, gxc, gxd;
        float mt = 0.f;
        if (tid < 32) {
            const float* gp = gates2 + (((size_t)s * 64 + cb) * 32 + tid) * 16;
            gxa = *(const float4*)(gp + 0);
            gxb = *(const float4*)(gp + 4);
            gxc = *(const float4*)(gp + 8);
            gxd = *(const float4*)(gp + 12);
            mt  = __ldg(mask + tid * SS + s);
        }

        if (t > 0) {
            if (tid < 64) {
                const int* p = fl_my + tid;
                while (ld_acquire_gpu(p) < t) { }
            }
            __syncthreads();

            // ---- hGEMM: 8 b x 4 r x 32 k per lane ----
            ull acc01[8], acc23[8];
#pragma unroll
            for (int i = 0; i < 8; ++i) { acc01[i] = 0ull; acc23[i] = 0ull; }

            const float4* hb = (const float4*)hx + ((size_t)dir * 2 + ((t - 1) & 1)) * 2048;

            float4 hcur[8];
#pragma unroll
            for (int i = 0; i < 8; ++i)
                hcur[i] = __ldcg(hb + i * 32 + hoff);

#pragma unroll
            for (int j = 0; j < 8; ++j) {
                float4 hnx[8];
                if (j < 7) {
#pragma unroll
                    for (int i = 0; i < 8; ++i)
                        hnx[i] = __ldcg(hb + (j + 1) * 256 + i * 32 + hoff);
                }
                // W for k = kc*32 + j*4 + kk
                ulonglong2 wv[4];
#pragma unroll
                for (int kk = 0; kk < 4; ++kk) {
                    int k = kc * 32 + j * 4 + kk;
                    int word = (k * 16 + rg * 4) ^ (kc << 2);
                    wv[kk] = *(const ulonglong2*)&sh_wp[word];
                }
#pragma unroll
                for (int i = 0; i < 8; ++i) {
                    const float* hf = &hcur[i].x;
#pragma unroll
                    for (int kk = 0; kk < 4; ++kk) {
                        ull hd = pack_dup(hf[kk]);
                        acc01[i] = ffma2(hd, wv[kk].x, acc01[i]);
                        acc23[i] = ffma2(hd, wv[kk].y, acc23[i]);
                    }
                }
                if (j < 7) {
#pragma unroll
                    for (int i = 0; i < 8; ++i) hcur[i] = hnx[i];
                }
            }

            // ---- butterfly reduce over kc (3 rounds) ----
#pragma unroll
            for (int d = 1; d < 8; d <<= 1) {
#pragma unroll
                for (int i = 0; i < 8; ++i) {
                    acc01[i] = add2(acc01[i], __shfl_xor_sync(0xffffffffu, acc01[i], d));
                    acc23[i] = add2(acc23[i], __shfl_xor_sync(0xffffffffu, acc23[i], d));
                }
            }
            if (kc == 0) {
#pragma unroll
                for (int i = 0; i < 8; ++i) {
                    int b = bg * 8 + i;
                    *(ull*)&sh_g[b * 18 + rg * 4 + 0] = acc01[i];
                    *(ull*)&sh_g[b * 18 + rg * 4 + 2] = acc23[i];
                }
            }
        } else {
            if (tid < 32) {
#pragma unroll
                for (int r = 0; r < 16; ++r) sh_g[tid * 18 + r] = 0.f;
            }
        }
        __syncthreads();

        // ---- cell (32 threads, one batch each, 4 units) ----
        if (tid < 32) {
            const float* gh = &sh_g[tid * 18];
            float4 hn4, cn4;
            float* hnp = &hn4.x;
            float* cnp = &cn4.x;
            float* csp = &c4.x;
            const float* gxi = &gxa.x;
            const float* gxf = &gxb.x;
            const float* gxg = &gxc.x;
            const float* gxo = &gxd.x;
#pragma unroll
            for (int u = 0; u < 4; ++u) {
                float ig = sigm_f(gxi[u] + gh[0  + u]);
                float fg = sigm_f(gxf[u] + gh[4  + u]);
                float gv = tanh_f(gxg[u] + gh[8  + u]);
                float og = sigm_f(gxo[u] + gh[12 + u]);
                float cn = fg * csp[u] + ig * gv;
                float hn = og * tanh_f(cn);
                hn *= mt;            // + h0*(1-mt), h0 == 0
                cn *= mt;            // + c0*(1-mt), c0 == 0
                csp[u] = cn;
                hnp[u] = hn;
                cnp[u] = cn;
            }
            // swizzled exchange buffer (critical path)
            ((float4*)hx)[((size_t)dir * 2 + (t & 1)) * 2048 + pidx] = hn4;
            // layer output (off critical path)
            size_t orow = out_bs ? ((size_t)tid * SS + s)
                                 : ((size_t)s * BB + tid);
            *(float4*)&xout[orow * H2 + dir * HH + u0] = hn4;
            if (t == SS - 1) {
                *(float4*)&hn_out[tid * H2 + dir * HH + u0] = hn4;
                *(float4*)&cn_out[tid * H2 + dir * HH + u0] = cn4;
            }
        }
        __syncthreads();   // h store happens-before the releases
        if (tid < 64) {
            st_release_gpu(fl_base + tid * 64 + cb, t + 1);
        }
    }
}

// --------------------------------------------------------------------------
extern "C" void kernel_launch(void* const* d_in, const int* in_sizes, int n_in,
                              void* d_out, int out_size)
{
    const float* inputs  = (const float*)d_in[0];
    const float* mask    = (const float*)d_in[1];
    const float* l0f_Wih = (const float*)d_in[2];
    const float* l0f_Whh = (const float*)d_in[3];
    const float* l0f_bih = (const float*)d_in[4];
    const float* l0f_bhh = (const float*)d_in[5];
    const float* l0b_Wih = (const float*)d_in[6];
    const float* l0b_Whh = (const float*)d_in[7];
    const float* l0b_bih = (const float*)d_in[8];
    const float* l0b_bhh = (const float*)d_in[9];
    const float* l1f_Wih = (const float*)d_in[10];
    const float* l1f_Whh = (const float*)d_in[11];
    const float* l1f_bih = (const float*)d_in[12];
    const float* l1f_bhh = (const float*)d_in[13];
    const float* l1b_Wih = (const float*)d_in[14];
    const float* l1b_Whh = (const float*)d_in[15];
    const float* l1b_bih = (const float*)d_in[16];
    const float* l1b_bhh = (const float*)d_in[17];
    float* out = (float*)d_out;

    float *p_gf, *p_gb, *p_x, *p_hx;
    int *p_fl;
    cudaGetSymbolAddress((void**)&p_gf, g_gates_f);
    cudaGetSymbolAddress((void**)&p_gb, g_gates_b);
    cudaGetSymbolAddress((void**)&p_x,  g_xout);
    cudaGetSymbolAddress((void**)&p_fl, g_flags);
    cudaGetSymbolAddress((void**)&p_hx, g_hx);

    const size_t HN_OFF = (size_t)BB * SS * H2;       // 16777216
    const size_t CN_OFF = HN_OFF + 2 * (size_t)BB * H2;
    float* hn0 = out + HN_OFF;
    float* hn1 = out + HN_OFF + (size_t)BB * H2;
    float* cn0 = out + CN_OFF;
    float* cn1 = out + CN_OFF + (size_t)BB * H2;

    zero_flags_k<<<64, 256>>>();

    dim3 ggrid(G4 / 128, (SS * BB) / 128, 2);   // (8, 256, 2) fwd+bwd merged

    // ---- layer 0 : recurrence output in [S,B,2H] scratch ----
    gates_gemm<<<ggrid, 256>>>(inputs,
                               l0f_Wih, l0f_bih, l0f_bhh,
                               l0b_Wih, l0b_bih, l0b_bhh,
                               p_gf, p_gb, 256, 0);
    lstm_recur<<<128, 128>>>(p_gf, p_gb, l0f_Whh, l0b_Whh, mask,
                             p_x, hn0, cn0, p_fl, p_hx, 0);

    // ---- layer 1 : recurrence writes final [B,S,2H] output directly ----
    gates_gemm<<<ggrid, 256>>>(p_x,
                               l1f_Wih, l1f_bih, l1f_bhh,
                               l1b_Wih, l1b_bih, l1b_bhh,
                               p_gf, p_gb, 512, 1);
    lstm_recur<<<128, 128>>>(p_gf, p_gb, l1f_Whh, l1b_Whh, mask,
                             out, hn1, cn1, p_fl + 2 * 64 * 64, p_hx, 1);
}

// round 12
// speedup vs baseline: 1.3563x; 1.3563x over previous
#include <cuda_runtime.h>
#include <cstdint>

#define BB   32
#define SS   1024
#define HH   256
#define G4   1024   // 4*H
#define H2   512    // 2*H

typedef unsigned long long ull;

// ---------------- f32x2 helpers (Blackwell packed fp32, 2 MAC/inst) -------
__device__ __forceinline__ ull ffma2(ull a, ull b, ull c)
{
    ull d;
    asm("fma.rn.f32x2 %0, %1, %2, %3;" : "=l"(d) : "l"(a), "l"(b), "l"(c));
    return d;
}
__device__ __forceinline__ ull add2(ull a, ull b)
{
    ull d;
    asm("add.rn.f32x2 %0, %1, %2;" : "=l"(d) : "l"(a), "l"(b));
    return d;
}
__device__ __forceinline__ ull pack_dup(float a)
{
    ull d;
    unsigned u = __float_as_uint(a);
    asm("mov.b64 %0, {%1, %1};" : "=l"(d) : "r"(u));
    return d;
}
__device__ __forceinline__ float2 unpack2(ull v)
{
    unsigned lo, hi;
    asm("mov.b64 {%0, %1}, %2;" : "=r"(lo), "=r"(hi) : "l"(v));
    return make_float2(__uint_as_float(lo), __uint_as_float(hi));
}

// ---------------- scoped release/acquire flag ops -------------------------
__device__ __forceinline__ void st_release_gpu(int* p, int v)
{
    asm volatile("st.release.gpu.global.u32 [%0], %1;" :: "l"(p), "r"(v) : "memory");
}
__device__ __forceinline__ int ld_acquire_gpu(const int* p)
{
    int v;
    asm volatile("ld.acquire.gpu.global.u32 %0, [%1];" : "=r"(v) : "l"(p) : "memory");
    return v;
}

// ------------------------- scratch (device globals; no allocs) -------------
// gates in recurrence layout: [s][cb(64)][b(32)][16]  (16 = gate*4+u)
__device__ float g_gates_f[(size_t)SS * BB * G4];   // 128 MB
__device__ float g_gates_b[(size_t)SS * BB * G4];   // 128 MB
__device__ float g_xout  [(size_t)SS * BB * H2];    //  64 MB (layer-0 output)
// replicated flags: [layer][dir][consumer(64)][producer(64)]
__device__ int   g_flags [2 * 2 * 64 * 64];
// h exchange: [dir][parity][b(32)][64] float4  (plain [b][k] row-major)
__device__ float g_hx    [2 * 2 * 32 * 256];

// --------------------------------------------------------------------------
__global__ void zero_flags_k()
{
    int i = blockIdx.x * blockDim.x + threadIdx.x;
    if (i < 2 * 2 * 64 * 64) g_flags[i] = 0;
}

// --------------------------------------------------------------------------
// x-GEMM (unchanged — measured 65.9% fma): tiles 128x128, f32x2, pipelined
// LDG; blockIdx.z selects fwd/bwd weight set + output buffer.
__global__ void __launch_bounds__(256) gates_gemm(
    const float* __restrict__ A,
    const float* __restrict__ Wf, const float* __restrict__ bihf, const float* __restrict__ bhhf,
    const float* __restrict__ Wb, const float* __restrict__ bihb, const float* __restrict__ bhhb,
    float* __restrict__ Cf, float* __restrict__ Cb,
    int K, int a_mode)
{
    __shared__ __align__(16) float As[16][132];
    __shared__ __align__(16) float Bs[16][132];

    const int z = blockIdx.z;
    const float* W   = z ? Wb   : Wf;
    const float* bih = z ? bihb : bihf;
    const float* bhh = z ? bhhb : bhhf;
    float* C2        = z ? Cb   : Cf;

    const int tid = threadIdx.x;
    const int tx = tid & 15;
    const int ty = tid >> 4;
    const int m0 = blockIdx.y * 128;
    const int n0 = blockIdx.x * 128;

    const int lr = tid >> 2;
    const int lc = (tid & 3) << 2;

    const float* arow0;
    const float* arow1;
    {
        int m  = m0 + lr;
        int m2 = m + 64;
        if (a_mode == 0) {
            int s = m >> 5, b = m & 31;
            arow0 = A + ((size_t)b * SS + s) * K;
            s = m2 >> 5; b = m2 & 31;
            arow1 = A + ((size_t)b * SS + s) * K;
        } else {
            arow0 = A + (size_t)m  * K;
            arow1 = A + (size_t)m2 * K;
        }
    }
    const float* wrow0 = W + (size_t)(n0 + lr)      * K;
    const float* wrow1 = W + (size_t)(n0 + lr + 64) * K;

    ull accp[8][4];
#pragma unroll
    for (int i = 0; i < 8; ++i)
#pragma unroll
        for (int j = 0; j < 4; ++j) accp[i][j] = 0ull;

    const int KT = K >> 4;

    float4 a0 = *(const float4*)(arow0 + lc);
    float4 a1 = *(const float4*)(arow1 + lc);
    float4 b0 = *(const float4*)(wrow0 + lc);
    float4 b1 = *(const float4*)(wrow1 + lc);

    for (int kt = 0; kt < KT; ++kt) {
        __syncthreads();
        As[lc + 0][lr] = a0.x; As[lc + 1][lr] = a0.y; As[lc + 2][lr] = a0.z; As[lc + 3][lr] = a0.w;
        As[lc + 0][lr + 64] = a1.x; As[lc + 1][lr + 64] = a1.y; As[lc + 2][lr + 64] = a1.z; As[lc + 3][lr + 64] = a1.w;
        Bs[lc + 0][lr] = b0.x; Bs[lc + 1][lr] = b0.y; Bs[lc + 2][lr] = b0.z; Bs[lc + 3][lr] = b0.w;
        Bs[lc + 0][lr + 64] = b1.x; Bs[lc + 1][lr + 64] = b1.y; Bs[lc + 2][lr + 64] = b1.z; Bs[lc + 3][lr + 64] = b1.w;
        __syncthreads();
        if (kt + 1 < KT) {
            int k0 = (kt + 1) << 4;
            a0 = *(const float4*)(arow0 + k0 + lc);
            a1 = *(const float4*)(arow1 + k0 + lc);
            b0 = *(const float4*)(wrow0 + k0 + lc);
            b1 = *(const float4*)(wrow1 + k0 + lc);
        }
#pragma unroll
        for (int k = 0; k < 16; ++k) {
            float4 af0 = *(const float4*)&As[k][ty * 4];
            float4 af1 = *(const float4*)&As[k][64 + ty * 4];
            ulonglong2 bv0 = *(const ulonglong2*)&Bs[k][tx * 4];
            ulonglong2 bv1 = *(const ulonglong2*)&Bs[k][64 + tx * 4];
            ull bp[4] = {bv0.x, bv0.y, bv1.x, bv1.y};
            float a_[8] = {af0.x, af0.y, af0.z, af0.w, af1.x, af1.y, af1.z, af1.w};
#pragma unroll
            for (int i = 0; i < 8; ++i) {
                ull ad = pack_dup(a_[i]);
#pragma unroll
                for (int j = 0; j < 4; ++j)
                    accp[i][j] = ffma2(ad, bp[j], accp[i][j]);
            }
        }
    }

#pragma unroll
    for (int qi = 0; qi < 2; ++qi) {
#pragma unroll
        for (int i = 0; i < 4; ++i) {
            int m = m0 + qi * 64 + ty * 4 + i;
            int s = m >> 5, b = m & 31;
#pragma unroll
            for (int qj = 0; qj < 2; ++qj) {
                int n = n0 + qj * 64 + tx * 4;
                float2 p0 = unpack2(accp[qi * 4 + i][qj * 2 + 0]);
                float2 p1 = unpack2(accp[qi * 4 + i][qj * 2 + 1]);
                float4 v;
                v.x = p0.x + bih[n + 0] + bhh[n + 0];
                v.y = p0.y + bih[n + 1] + bhh[n + 1];
                v.z = p1.x + bih[n + 2] + bhh[n + 2];
                v.w = p1.y + bih[n + 3] + bhh[n + 3];
                int g  = n >> 8;
                int ub = (n & 255) >> 2;
                *(float4*)&C2[(((size_t)s * 64 + ub) * 32 + b) * 16 + g * 4] = v;
            }
        }
    }
}

// --------------------------------------------------------------------------
// Recurrence v4: R8 sync skeleton + register-resident W + k-packed f32x2.
// 128 CTAs (blockIdx<64: fwd), 256 threads = 8 warps.
// warp = batch group bg (4 batches); lane = rg(4 gates) x ks(8 k-slices).
// Each lane: acc[4b][4r] over 32 k (packed pairs); W slice (4 rows x 32 k)
// lives in 64 f32x2 REGISTERS for the whole kernel. h staged to smem once
// per step (swizzled layout -> LDS.64 phases are broadcast + conflict-free).
// Butterfly shfl_xor over ks reduces K; lanes ks==0 write gates to smem.
__device__ __forceinline__ float sigm_f(float x)
{
    float e = __expf(-x);
    return __fdividef(1.f, 1.f + e);
}
__device__ __forceinline__ float tanh_f(float x)
{
    float xc = fminf(fmaxf(x, -30.f), 30.f);
    float e = __expf(-2.f * xc);
    return __fdividef(1.f - e, 1.f + e);
}

__global__ void __launch_bounds__(256) lstm_recur(
    const float* __restrict__ gatesF2, const float* __restrict__ gatesB2,
    const float* __restrict__ WhhF, const float* __restrict__ WhhB,
    const float* __restrict__ mask,
    float* __restrict__ xout,
    float* __restrict__ hn_out, float* __restrict__ cn_out,
    int* __restrict__ flags,        // [dir][cons64][prod64]
    float* __restrict__ hx,         // [dir][parity][32][64] float4
    int out_bs)
{
    __shared__ __align__(16) float4 sh_h4[32 * 66];   // swizzled h, pad 66
    __shared__ __align__(16) float  sh_g[32 * 20];    // gates, stride 20

    const int tid  = threadIdx.x;
    const int dir  = blockIdx.x >> 6;
    const int cb   = blockIdx.x & 63;
    const int u0   = cb * 4;
    const int bg   = tid >> 5;        // warp: batch group (8)
    const int lane = tid & 31;
    const int rg   = lane >> 3;       // gate (4)
    const int ks   = lane & 7;        // k slice (8): k = ks*32 .. +31

    const float* gates2 = dir ? gatesB2 : gatesF2;
    const float* Whh    = dir ? WhhB    : WhhF;
    int* fl_my   = flags + (dir * 64 + cb) * 64;
    int* fl_base = flags + dir * 64 * 64;

    // ---- one-time: W slice (rows rg*4+r = gate rg, unit r; k in slice) ----
    // w[r][k2] = (W[row][ks*32+2*k2], W[row][ks*32+2*k2+1]) packed.
    ull w[4][16];
#pragma unroll
    for (int r = 0; r < 4; ++r) {
        const float* wr = Whh + (size_t)(rg * HH + u0 + r) * HH + ks * 32;
#pragma unroll
        for (int f = 0; f < 8; ++f) {
            ulonglong2 v = *(const ulonglong2*)(wr + f * 4);
            w[r][f * 2 + 0] = v.x;
            w[r][f * 2 + 1] = v.y;
        }
    }

    float4 c4 = make_float4(0.f, 0.f, 0.f, 0.f);   // cell state (tid<32)

    for (int t = 0; t < SS; ++t) {
        const int s = dir ? (SS - 1 - t) : t;

        // cell-thread early loads (independent of the wait)
        float4 gxa, gxb, gxc, gxd;
        float mt = 0.f;
        if (tid < 32) {
            const float* gp = gates2 + (((size_t)s * 64 + cb) * 32 + tid) * 16;
            gxa = *(const float4*)(gp + 0);
            gxb = *(const float4*)(gp + 4);
            gxc = *(const float4*)(gp + 8);
            gxd = *(const float4*)(gp + 12);
            mt  = __ldg(mask + tid * SS + s);
        }

        if (t > 0) {
            if (tid < 64) {
                const int* p = fl_my + tid;
                while (ld_acquire_gpu(p) < t) { __nanosleep(64); }
            }
            __syncthreads();

            // stage h(t-1) into swizzled smem: src [b][k] row-major float4
            const float4* src = (const float4*)hx + ((size_t)dir * 2 + ((t - 1) & 1)) * 2048;
            for (int q = tid; q < 2048; q += 256) {
                int b  = q >> 6;
                int k4 = q & 63;
                int kss = k4 >> 3, j = k4 & 7;
                float4 v = __ldcg(src + q);
                sh_h4[b * 66 + kss * 8 + ((j + kss) & 7)] = v;
            }
            __syncthreads();

            // ---- hGEMM: acc[4b][4r] over k-slice, packed pairs ----
            ull acc[4][4];
#pragma unroll
            for (int i = 0; i < 4; ++i)
#pragma unroll
                for (int r = 0; r < 4; ++r) acc[i][r] = 0ull;

#pragma unroll
            for (int k2 = 0; k2 < 16; ++k2) {
                const int co = (((k2 >> 1) + ks) & 7) * 2 + (k2 & 1);
#pragma unroll
                for (int i = 0; i < 4; ++i) {
                    const ull* hp = (const ull*)&sh_h4[(bg * 4 + i) * 66 + ks * 8];
                    ull h = hp[co];
#pragma unroll
                    for (int r = 0; r < 4; ++r)
                        acc[i][r] = ffma2(h, w[r][k2], acc[i][r]);
                }
            }

            // ---- butterfly reduce over ks (3 rounds) ----
#pragma unroll
            for (int d = 1; d < 8; d <<= 1) {
#pragma unroll
                for (int i = 0; i < 4; ++i)
#pragma unroll
                    for (int r = 0; r < 4; ++r)
                        acc[i][r] = add2(acc[i][r],
                                         __shfl_xor_sync(0xffffffffu, acc[i][r], d));
            }
            if (ks == 0) {
#pragma unroll
                for (int i = 0; i < 4; ++i)
#pragma unroll
                    for (int r = 0; r < 4; ++r) {
                        float2 u = unpack2(acc[i][r]);
                        sh_g[(bg * 4 + i) * 20 + rg * 4 + r] = u.x + u.y;
                    }
            }
        } else {
            if (tid < 32) {
#pragma unroll
                for (int r = 0; r < 16; ++r) sh_g[tid * 20 + r] = 0.f;
            }
        }
        __syncthreads();

        // ---- cell (32 threads, one batch each, 4 units) ----
        if (tid < 32) {
            const float* gh = &sh_g[tid * 20];
            float4 hn4, cn4;
            float* hnp = &hn4.x;
            float* cnp = &cn4.x;
            float* csp = &c4.x;
            const float* gxi = &gxa.x;
            const float* gxf = &gxb.x;
            const float* gxg = &gxc.x;
            const float* gxo = &gxd.x;
#pragma unroll
            for (int u = 0; u < 4; ++u) {
                float ig = sigm_f(gxi[u] + gh[0  + u]);
                float fg = sigm_f(gxf[u] + gh[4  + u]);
                float gv = tanh_f(gxg[u] + gh[8  + u]);
                float og = sigm_f(gxo[u] + gh[12 + u]);
                float cn = fg * csp[u] + ig * gv;
                float hn = og * tanh_f(cn);
                hn *= mt;            // + h0*(1-mt), h0 == 0
                cn *= mt;            // + c0*(1-mt), c0 == 0
                csp[u] = cn;
                hnp[u] = hn;
                cnp[u] = cn;
            }
            // exchange buffer (critical path): [b][k] float4 index b*64+cb
            ((float4*)hx)[((size_t)dir * 2 + (t & 1)) * 2048 + tid * 64 + cb] = hn4;
            // layer output (off critical path)
            size_t orow = out_bs ? ((size_t)tid * SS + s)
                                 : ((size_t)s * BB + tid);
            *(float4*)&xout[orow * H2 + dir * HH + u0] = hn4;
            if (t == SS - 1) {
                *(float4*)&hn_out[tid * H2 + dir * HH + u0] = hn4;
                *(float4*)&cn_out[tid * H2 + dir * HH + u0] = cn4;
            }
        }
        __syncthreads();   // h stores happen-before the releases
        if (tid < 64) {
            st_release_gpu(fl_base + tid * 64 + cb, t + 1);
        }
    }
}

// --------------------------------------------------------------------------
extern "C" void kernel_launch(void* const* d_in, const int* in_sizes, int n_in,
                              void* d_out, int out_size)
{
    const float* inputs  = (const float*)d_in[0];
    const float* mask    = (const float*)d_in[1];
    const float* l0f_Wih = (const float*)d_in[2];
    const float* l0f_Whh = (const float*)d_in[3];
    const float* l0f_bih = (const float*)d_in[4];
    const float* l0f_bhh = (const float*)d_in[5];
    const float* l0b_Wih = (const float*)d_in[6];
    const float* l0b_Whh = (const float*)d_in[7];
    const float* l0b_bih = (const float*)d_in[8];
    const float* l0b_bhh = (const float*)d_in[9];
    const float* l1f_Wih = (const float*)d_in[10];
    const float* l1f_Whh = (const float*)d_in[11];
    const float* l1f_bih = (const float*)d_in[12];
    const float* l1f_bhh = (const float*)d_in[13];
    const float* l1b_Wih = (const float*)d_in[14];
    const float* l1b_Whh = (const float*)d_in[15];
    const float* l1b_bih = (const float*)d_in[16];
    const float* l1b_bhh = (const float*)d_in[17];
    float* out = (float*)d_out;

    float *p_gf, *p_gb, *p_x, *p_hx;
    int *p_fl;
    cudaGetSymbolAddress((void**)&p_gf, g_gates_f);
    cudaGetSymbolAddress((void**)&p_gb, g_gates_b);
    cudaGetSymbolAddress((void**)&p_x,  g_xout);
    cudaGetSymbolAddress((void**)&p_fl, g_flags);
    cudaGetSymbolAddress((void**)&p_hx, g_hx);

    const size_t HN_OFF = (size_t)BB * SS * H2;       // 16777216
    const size_t CN_OFF = HN_OFF + 2 * (size_t)BB * H2;
    float* hn0 = out + HN_OFF;
    float* hn1 = out + HN_OFF + (size_t)BB * H2;
    float* cn0 = out + CN_OFF;
    float* cn1 = out + CN_OFF + (size_t)BB * H2;

    zero_flags_k<<<64, 256>>>();

    dim3 ggrid(G4 / 128, (SS * BB) / 128, 2);   // (8, 256, 2) fwd+bwd merged

    // ---- layer 0 : recurrence output in [S,B,2H] scratch ----
    gates_gemm<<<ggrid, 256>>>(inputs,
                               l0f_Wih, l0f_bih, l0f_bhh,
                               l0b_Wih, l0b_bih, l0b_bhh,
                               p_gf, p_gb, 256, 0);
    lstm_recur<<<128, 256>>>(p_gf, p_gb, l0f_Whh, l0b_Whh, mask,
                             p_x, hn0, cn0, p_fl, p_hx, 0);

    // ---- layer 1 : recurrence writes final [B,S,2H] output directly ----
    gates_gemm<<<ggrid, 256>>>(p_x,
                               l1f_Wih, l1f_bih, l1f_bhh,
                               l1b_Wih, l1b_bih, l1b_bhh,
                               p_gf, p_gb, 512, 1);
    lstm_recur<<<128, 256>>>(p_gf, p_gb, l1f_Whh, l1b_Whh, mask,
                             out, hn1, cn1, p_fl + 2 * 64 * 64, p_hx, 1);
}